// round 5
// baseline (speedup 1.0000x reference)
#include <cuda_runtime.h>
#include <cstdint>

// Conv4D via mma.sync tf32 (portable sm_80+ PTX).
// x(8,16,32,24,24,24) NCLDHW * W(32,16,3,3,3,3) OILDHW -> out(8,32,30,22,22,22), +3*b.
//
// R5: (a) prepass converts x and W to tf32 bits in __device__ scratch (no cvt in
// mainloop), W re-laid-out per (lk,dk) slab for float4 staging; (b) tap loop fully
// unrolled; (c) smem cut to 114.3KB (single W buffer, staged after compute) so
// 2 CTAs/SM co-reside -> 4 warps/SMSP for latency hiding.

#define XROW 712                           // floats per k-row, == 8 mod 32 (bank-unique)
#define XBUF_BYTES (16 * XROW * 4)         // 45568
#define WROW 40                            // == 8 mod 32
#define WBUF_BYTES (9 * 16 * WROW * 4)     // 23040
#define OFF_X0 0
#define OFF_X1 XBUF_BYTES
#define OFF_W  (2 * XBUF_BYTES)            // 91136
#define OFF_BS (OFF_W + WBUF_BYTES)        // 114176
#define SMEM_TOTAL (OFF_BS + 128)          // 114304  (x2 = 228608 <= 233472)

#define CI_STRIDE 442368                   // 32*24*24*24 floats between ci planes
#define L_STRIDE  13824                    // 24*24*24
#define OUT_CO_STRIDE 319440               // 30*22*22*22

__device__ uint32_t g_xt[56623104];        // x as tf32 bits (226MB scratch)
__device__ uint32_t g_wt[41472];           // W as tf32 bits, layout [s][tap][ci][co]

static __device__ __forceinline__ uint32_t s2u(const void* p) {
    uint32_t a;
    asm("{ .reg .u64 t; cvta.to.shared.u64 t, %1; cvt.u32.u64 %0, t; }" : "=r"(a) : "l"(p));
    return a;
}
static __device__ __forceinline__ uint32_t tf32rn(float f) {
    uint32_t o;
    asm("cvt.rna.tf32.f32 %0, %1;" : "=r"(o) : "f"(f));
    return o;
}
static __device__ __forceinline__ void cp16(uint32_t dst, const void* src) {
    asm volatile("cp.async.cg.shared.global [%0], [%1], 16;" :: "r"(dst), "l"(src) : "memory");
}

#define MMA_TF32(d, a0, a1, a2, a3, b0, b1) \
    asm volatile("mma.sync.aligned.m16n8k8.row.col.f32.tf32.tf32.f32 " \
        "{%0,%1,%2,%3}, {%4,%5,%6,%7}, {%8,%9}, {%0,%1,%2,%3};" \
        : "+f"((d)[0]), "+f"((d)[1]), "+f"((d)[2]), "+f"((d)[3]) \
        : "r"(a0), "r"(a1), "r"(a2), "r"(a3), "r"(b0), "r"(b1))

// ---- prepass: x -> tf32 bits (float4 granularity, exact cover) ----
__global__ __launch_bounds__(256)
void prep_x_kernel(const float* __restrict__ x) {
    size_t i = ((size_t)blockIdx.x * 256 + threadIdx.x) * 4;
    float4 v = *(const float4*)(x + i);
    uint4 o;
    o.x = tf32rn(v.x); o.y = tf32rn(v.y); o.z = tf32rn(v.z); o.w = tf32rn(v.w);
    *(uint4*)(g_xt + i) = o;
}

// ---- prepass: W -> tf32 bits, layout [(lk*3+dk)][tap(hk*3+wk)][ci][co] ----
__global__ __launch_bounds__(256)
void prep_w_kernel(const float* __restrict__ W) {
    int e   = blockIdx.x * 256 + threadIdx.x;   // 0..41471
    int co  = e & 31;
    int ci  = (e >> 5) & 15;
    int t9  = e >> 9;                            // 0..80 = s*9+tap
    int s   = t9 / 9;
    int tap = t9 - 9 * s;
    int lk = s / 3,  dk = s - 3 * lk;
    int hk = tap / 3, wk = tap - 3 * hk;
    g_wt[e] = tf32rn(W[(size_t)(co * 16 + ci) * 81 + lk * 27 + dk * 9 + hk * 3 + wk]);
}

extern __shared__ char smem[];

__global__ __launch_bounds__(256, 2)
void conv4d_mma_kernel(const float* __restrict__ b, float* __restrict__ out)
{
    const int d_out = blockIdx.x;   // 0..21
    const int l_out = blockIdx.y;   // 0..29
    const int n     = blockIdx.z;   // 0..7
    const int tid   = threadIdx.x;
    const int wid   = tid >> 5;
    const int lid   = tid & 31;
    const int c     = lid & 3;
    const int g     = lid >> 2;
    const uint32_t sb = s2u(smem);

    if (tid < 32) ((float*)(smem + OFF_BS))[tid] = 3.0f * b[tid];

    auto stage_x = [&](int s) {
        const int lk = s / 3, dk = s - 3 * lk;
        const uint32_t xoff = sb + ((s & 1) ? OFF_X1 : OFF_X0);
        const uint32_t* xb = g_xt + ((size_t)(n * 16) * 32 + (l_out + lk)) * L_STRIDE
                                  + (d_out + dk) * 576;
        #pragma unroll
        for (int j = 0; j < 9; j++) {
            int it = tid + j * 256;          // 0..2303
            int ci = it / 144;
            int ch = it - ci * 144;
            cp16(xoff + (uint32_t)(ci * (XROW * 4) + ch * 16),
                 xb + (size_t)ci * CI_STRIDE + ch * 4);
        }
    };
    auto stage_w = [&](int s) {
        const uint32_t* wsrc = g_wt + s * 4608;
        #pragma unroll
        for (int j = 0; j < 5; j++) {
            int it = tid + j * 256;          // 0..1151 chunks
            if (it < 1152) {
                int row = it >> 3;           // tap*16+ci
                int co4 = it & 7;
                cp16(sb + OFF_W + (uint32_t)(row * 160 + co4 * 16),
                     wsrc + row * 32 + co4 * 4);
            }
        }
    };

    float acc[5][4][4];
    #pragma unroll
    for (int mt = 0; mt < 5; mt++)
        #pragma unroll
        for (int nt = 0; nt < 4; nt++)
            #pragma unroll
            for (int q = 0; q < 4; q++)
                acc[mt][nt][q] = 0.0f;

    stage_x(0); stage_w(0);
    asm volatile("cp.async.commit_group;" ::: "memory");
    asm volatile("cp.async.wait_group 0;" ::: "memory");
    __syncthreads();

    const uint32_t* wsu = (const uint32_t*)(smem + OFF_W);

    for (int s = 0; s < 9; s++) {
        if (s < 8) {
            stage_x(s + 1);                  // other x buffer; latency hides over compute
            asm volatile("cp.async.commit_group;" ::: "memory");
        }

        const uint32_t* xsu = (const uint32_t*)(smem + ((s & 1) ? OFF_X1 : OFF_X0));

        #pragma unroll
        for (int tap = 0; tap < 9; tap++) {
            const int hk = tap / 3;
            const int tapoff = hk * 24 + (tap - 3 * hk);
            #pragma unroll
            for (int kc = 0; kc < 2; kc++) {
                const uint32_t* wrow = wsu + (tap * 16 + kc * 8 + c) * WROW + g;
                uint32_t breg[4][2];
                #pragma unroll
                for (int nt = 0; nt < 4; nt++) {
                    breg[nt][0] = wrow[nt * 8];
                    breg[nt][1] = wrow[4 * WROW + nt * 8];
                }
                const uint32_t* xrow = xsu + (kc * 8 + c) * XROW + g + tapoff;
                #pragma unroll
                for (int mt = 0; mt < 5; mt++) {
                    const int m0 = (wid * 5 + mt) * 16;
                    uint32_t a0 = xrow[m0];
                    uint32_t a1 = xrow[m0 + 8];
                    uint32_t a2 = xrow[4 * XROW + m0];
                    uint32_t a3 = xrow[4 * XROW + m0 + 8];
                    #pragma unroll
                    for (int nt = 0; nt < 4; nt++)
                        MMA_TF32(acc[mt][nt], a0, a1, a2, a3, breg[nt][0], breg[nt][1]);
                }
            }
        }

        __syncthreads();                     // all warps done reading W (and x[s])
        if (s < 8) {
            stage_w(s + 1);                  // single W buffer, safe after sync
            asm volatile("cp.async.commit_group;" ::: "memory");
            asm volatile("cp.async.wait_group 0;" ::: "memory");   // x(s+1) long done; W just issued
            __syncthreads();
        }
    }

    // ---- epilogue: D row = g (+8), col = 2c (+1) ----
    const float* bs = (const float*)(smem + OFF_BS);
    const int spat = l_out * 10648 + d_out * 484;
    #pragma unroll
    for (int mt = 0; mt < 5; mt++) {
        const int mb = (wid * 5 + mt) * 16 + g;
        #pragma unroll
        for (int hm = 0; hm < 2; hm++) {
            int m = mb + 8 * hm;
            int h = m / 24;
            int w = m - 24 * h;
            if (h < 22 && w < 22) {
                size_t pos = (size_t)spat + h * 22 + w;
                #pragma unroll
                for (int nt = 0; nt < 4; nt++) {
                    #pragma unroll
                    for (int hc = 0; hc < 2; hc++) {
                        int co = nt * 8 + 2 * c + hc;
                        out[(size_t)(n * 32 + co) * OUT_CO_STRIDE + pos] =
                            acc[mt][nt][hm * 2 + hc] + bs[co];
                    }
                }
            }
        }
    }
}

extern "C" void kernel_launch(void* const* d_in, const int* in_sizes, int n_in,
                              void* d_out, int out_size)
{
    const float* x = (const float*)d_in[0];
    const float* W = (const float*)d_in[1];
    const float* b = (const float*)d_in[2];
    float* out = (float*)d_out;

    prep_x_kernel<<<55296, 256>>>(x);       // 56623104/4 float4 chunks, exact
    prep_w_kernel<<<162, 256>>>(W);         // 41472 elements, exact

    cudaFuncSetAttribute(conv4d_mma_kernel,
                         cudaFuncAttributeMaxDynamicSharedMemorySize, SMEM_TOTAL);
    dim3 grid(22, 30, 8);                   // (d_out, l_out, n)
    conv4d_mma_kernel<<<grid, 256, SMEM_TOTAL>>>(b, out);
}

// round 6
// speedup vs baseline: 1.5775x; 1.5775x over previous
#include <cuda_runtime.h>
#include <cstdint>

// Conv4D via mma.sync tf32 (portable sm_80+ PTX; tcgen05 not available at
// compute_103 target).
// x(8,16,32,24,24,24) NCLDHW * W(32,16,3,3,3,3) OILDHW -> out(8,32,30,22,22,22), +3*b.
//
// R6: prepass repacks x -> g_xp[n][l][d][m=hw 576][16 ci, k-pair interleaved]
// and W -> g_wp[s][tap][co][16 k-pair interleaved], tf32-rounded bits.
// Fragment loads become single ld.shared.v2.u32 (conflict-free):
//   A: x smem m-major, 32B/row per k-octet (stride 8 floats)
//   B: W smem rows padded to 24 floats
// Tile-interleaved M map (m0=(wid+8*mt)*16): warps 1-7 do 4 m-tiles, warp 0 does 5.
// Double-buffered x and W via cp.async.

#define XBUF 22016                 // 688 rows * 32B, one k-octet
#define OFF_X0 0
#define OFF_X1 44032               // 2 octets per buffer
#define OFF_W0 88064               // 288 rows * 96B = 27648
#define OFF_W1 115712
#define OFF_BS 143360
#define SMEM_TOTAL 143488

#define L_STRIDE 13824             // 24*24*24
#define OUT_CO_STRIDE 319440       // 30*22*22*22

__device__ uint32_t g_xp[56623104];    // [n][l][d][m][16]
__device__ uint32_t g_wp[41472];       // [s][tap][co][16]

static __device__ __forceinline__ uint32_t s2u(const void* p) {
    uint32_t a;
    asm("{ .reg .u64 t; cvta.to.shared.u64 t, %1; cvt.u32.u64 %0, t; }" : "=r"(a) : "l"(p));
    return a;
}
static __device__ __forceinline__ uint32_t tf32rn(float f) {
    uint32_t o;
    asm("cvt.rna.tf32.f32 %0, %1;" : "=r"(o) : "f"(f));
    return o;
}
static __device__ __forceinline__ void cp16(uint32_t dst, const void* src) {
    asm volatile("cp.async.cg.shared.global [%0], [%1], 16;" :: "r"(dst), "l"(src) : "memory");
}
static __device__ __forceinline__ void lds2(uint32_t& r0, uint32_t& r1, uint32_t a) {
    asm volatile("ld.shared.v2.u32 {%0,%1}, [%2];" : "=r"(r0), "=r"(r1) : "r"(a));
}

#define MMA_TF32(d, a0, a1, a2, a3, b0, b1) \
    asm volatile("mma.sync.aligned.m16n8k8.row.col.f32.tf32.tf32.f32 " \
        "{%0,%1,%2,%3}, {%4,%5,%6,%7}, {%8,%9}, {%0,%1,%2,%3};" \
        : "+f"((d)[0]), "+f"((d)[1]), "+f"((d)[2]), "+f"((d)[3]) \
        : "r"(a0), "r"(a1), "r"(a2), "r"(a3), "r"(b0), "r"(b1))

// ---- prepass: x -> tf32 bits, pair-interleaved ci within (n,l,d,m) rows ----
__global__ __launch_bounds__(256)
void prep_x_kernel(const float* __restrict__ x) {
    const int d = blockIdx.x, l = blockIdx.y, n = blockIdx.z;
    const int tid = threadIdx.x;
    const size_t src0 = ((size_t)(n * 16) * 32 + l) * L_STRIDE + d * 576;
    uint32_t* dst0 = g_xp + (((size_t)(n * 32 + l) * 24 + d) * 576) * 16;
    for (int m = tid; m < 576; m += 256) {
        uint32_t v[16];
        #pragma unroll
        for (int ci = 0; ci < 16; ci++) {
            int o = ci >> 3, r = ci & 7, p = r & 3, s = r >> 2;
            v[o * 8 + p * 2 + s] = tf32rn(x[src0 + (size_t)ci * (32 * L_STRIDE) + m]);
        }
        uint32_t* dr = dst0 + m * 16;
        #pragma unroll
        for (int q = 0; q < 4; q++)
            *(uint4*)(dr + q * 4) = make_uint4(v[q*4], v[q*4+1], v[q*4+2], v[q*4+3]);
    }
}

// ---- prepass: W -> tf32 bits, [s][tap][co][16 pair-interleaved] ----
__global__ __launch_bounds__(256)
void prep_w_kernel(const float* __restrict__ W) {
    int e = blockIdx.x * 256 + threadIdx.x;     // 0..41471
    int off = e & 15;
    int co  = (e >> 4) & 31;
    int t9  = e >> 9;                            // s*9+tap
    int s   = t9 / 9, tap = t9 - 9 * s;
    int lk = s / 3,  dk = s - 3 * lk;
    int hk = tap / 3, wk = tap - 3 * hk;
    int kc = off >> 3, q = off & 7, p = q >> 1, sl = q & 1;
    int ci = kc * 8 + sl * 4 + p;
    g_wp[e] = tf32rn(W[(size_t)(co * 16 + ci) * 81 + lk * 27 + dk * 9 + hk * 3 + wk]);
}

extern __shared__ char smem[];

__global__ __launch_bounds__(256)
void conv4d_mma_kernel(const float* __restrict__ b, float* __restrict__ out)
{
    const int d_out = blockIdx.x;   // 0..21
    const int l_out = blockIdx.y;   // 0..29
    const int n     = blockIdx.z;   // 0..7
    const int tid   = threadIdx.x;
    const int wid   = tid >> 5;
    const int lid   = tid & 31;
    const int c     = lid & 3;
    const int g     = lid >> 2;
    const uint32_t sb = s2u(smem);

    if (tid < 32) ((float*)(smem + OFF_BS))[tid] = 3.0f * b[tid];

    auto stage = [&](int s) {
        const int lk = s / 3, dk = s - 3 * lk;
        const uint32_t xo = sb + ((s & 1) ? OFF_X1 : OFF_X0);
        const uint32_t wo = sb + ((s & 1) ? OFF_W1 : OFF_W0);
        const uint32_t* xs = g_xp + (((size_t)(n * 32 + (l_out + lk)) * 24 + (d_out + dk)) * 576) * 16;
        #pragma unroll
        for (int j9 = 0; j9 < 9; j9++) {
            int j = tid + j9 * 256;              // 0..2303
            int m = j >> 2, q = j & 3;
            cp16(xo + (q >= 2 ? XBUF : 0) + (uint32_t)(m * 32 + (q & 1) * 16),
                 xs + (size_t)j * 4);
        }
        const uint32_t* wsrc = g_wp + s * 4608;
        #pragma unroll
        for (int j5 = 0; j5 < 5; j5++) {
            int j = tid + j5 * 256;              // 0..1151
            if (j < 1152) {
                int row = j >> 2, q = j & 3;
                cp16(wo + (uint32_t)(row * 96 + q * 16), wsrc + j * 4);
            }
        }
        asm volatile("cp.async.commit_group;" ::: "memory");
    };

    float acc[5][4][4];
    #pragma unroll
    for (int mt = 0; mt < 5; mt++)
        #pragma unroll
        for (int nt = 0; nt < 4; nt++)
            #pragma unroll
            for (int q = 0; q < 4; q++)
                acc[mt][nt][q] = 0.0f;

    stage(0);

    const int ntile = (wid == 0) ? 5 : 4;

    for (int s = 0; s < 9; s++) {
        if (s < 8) {
            stage(s + 1);
            asm volatile("cp.async.wait_group 1;" ::: "memory");
        } else {
            asm volatile("cp.async.wait_group 0;" ::: "memory");
        }
        __syncthreads();

        const uint32_t xb = sb + ((s & 1) ? OFF_X1 : OFF_X0);
        const uint32_t wb = sb + ((s & 1) ? OFF_W1 : OFF_W0);

        #pragma unroll
        for (int tap = 0; tap < 9; tap++) {
            const int hk = tap / 3;
            const int tapoff = hk * 24 + (tap - 3 * hk);
            #pragma unroll
            for (int kc = 0; kc < 2; kc++) {
                // B: row = tap*32 + nt*8 + g, stride 24 floats; pair at kc*8+2c
                uint32_t breg[4][2];
                const uint32_t wrow = wb + (uint32_t)(((tap * 32 + g) * 24 + kc * 8 + c * 2) * 4);
                #pragma unroll
                for (int nt = 0; nt < 4; nt++)
                    lds2(breg[nt][0], breg[nt][1], wrow + nt * (8 * 24 * 4));
                // A: octet buffer kc, row m0+g+tapoff, pair c
                const uint32_t xrow = xb + (kc ? XBUF : 0) + (uint32_t)((g + tapoff) * 32 + c * 8);
                for (int mt = 0; mt < ntile; mt++) {
                    const int m0 = (wid + 8 * mt) * 16;
                    uint32_t a0, a1, a2, a3;
                    lds2(a0, a2, xrow + m0 * 32);
                    lds2(a1, a3, xrow + (m0 + 8) * 32);
                    #pragma unroll
                    for (int nt = 0; nt < 4; nt++)
                        MMA_TF32(acc[mt][nt], a0, a1, a2, a3, breg[nt][0], breg[nt][1]);
                }
            }
        }
        __syncthreads();
    }

    // ---- epilogue ----
    const float* bs = (const float*)(smem + OFF_BS);
    const int spat = l_out * 10648 + d_out * 484;
    for (int mt = 0; mt < ntile; mt++) {
        const int mb = (wid + 8 * mt) * 16 + g;
        #pragma unroll
        for (int hm = 0; hm < 2; hm++) {
            int m = mb + 8 * hm;
            int h = m / 24;
            int w = m - 24 * h;
            if (h < 22 && w < 22) {
                size_t pos = (size_t)spat + h * 22 + w;
                #pragma unroll
                for (int nt = 0; nt < 4; nt++) {
                    #pragma unroll
                    for (int hc = 0; hc < 2; hc++) {
                        int co = nt * 8 + 2 * c + hc;
                        out[(size_t)(n * 32 + co) * OUT_CO_STRIDE + pos] =
                            acc[mt][nt][hm * 2 + hc] + bs[co];
                    }
                }
            }
        }
    }
}

extern "C" void kernel_launch(void* const* d_in, const int* in_sizes, int n_in,
                              void* d_out, int out_size)
{
    const float* x = (const float*)d_in[0];
    const float* W = (const float*)d_in[1];
    const float* b = (const float*)d_in[2];
    float* out = (float*)d_out;

    dim3 pgrid(24, 32, 8);
    prep_x_kernel<<<pgrid, 256>>>(x);
    prep_w_kernel<<<162, 256>>>(W);

    cudaFuncSetAttribute(conv4d_mma_kernel,
                         cudaFuncAttributeMaxDynamicSharedMemorySize, SMEM_TOTAL);
    dim3 grid(22, 30, 8);   // (d_out, l_out, n)
    conv4d_mma_kernel<<<grid, 256, SMEM_TOTAL>>>(b, out);
}

// round 7
// speedup vs baseline: 1.7997x; 1.1409x over previous
#include <cuda_runtime.h>
#include <cstdint>

// Conv4D via mma.sync tf32 (portable sm_80+ PTX).
// x(8,16,32,24,24,24) NCLDHW * W(32,16,3,3,3,3) OILDHW -> out(8,32,30,22,22,22), +3*b.
//
// R7: 384 threads (12 warps, 3/SMSP); k-quad layout -> every fragment load is one
// ld.shared.v4.u32 serving BOTH k-steps; round-robin tile map (33 m-tiles);
// double-buffered x/W via cp.async; smem 111.3KB.

#define XBUF 37120                 // 580 rows * 64B
#define OFF_X0 0
#define OFF_X1 37120
#define OFF_W0 74240               // 288 rows * 64B = 18432
#define OFF_W1 92672
#define OFF_BS 111104
#define SMEM_TOTAL 111232

#define L_STRIDE 13824             // 24*24*24
#define OUT_CO_STRIDE 319440       // 30*22*22*22

__device__ uint32_t g_xp[56623104];    // [n][l][d][m=576][16 ci quad-interleaved]
__device__ uint32_t g_wp[41472];       // [s][tap][co][16 ci quad-interleaved]

static __device__ __forceinline__ uint32_t s2u(const void* p) {
    uint32_t a;
    asm("{ .reg .u64 t; cvta.to.shared.u64 t, %1; cvt.u32.u64 %0, t; }" : "=r"(a) : "l"(p));
    return a;
}
static __device__ __forceinline__ uint32_t tf32rn(float f) {
    uint32_t o;
    asm("cvt.rna.tf32.f32 %0, %1;" : "=r"(o) : "f"(f));
    return o;
}
static __device__ __forceinline__ void cp16(uint32_t dst, const void* src) {
    asm volatile("cp.async.cg.shared.global [%0], [%1], 16;" :: "r"(dst), "l"(src) : "memory");
}
static __device__ __forceinline__ void lds4(uint32_t& r0, uint32_t& r1, uint32_t& r2, uint32_t& r3, uint32_t a) {
    asm volatile("ld.shared.v4.u32 {%0,%1,%2,%3}, [%4];" : "=r"(r0), "=r"(r1), "=r"(r2), "=r"(r3) : "r"(a));
}

#define MMA_TF32(d, a0, a1, a2, a3, b0, b1) \
    asm volatile("mma.sync.aligned.m16n8k8.row.col.f32.tf32.tf32.f32 " \
        "{%0,%1,%2,%3}, {%4,%5,%6,%7}, {%8,%9}, {%0,%1,%2,%3};" \
        : "+f"((d)[0]), "+f"((d)[1]), "+f"((d)[2]), "+f"((d)[3]) \
        : "r"(a0), "r"(a1), "r"(a2), "r"(a3), "r"(b0), "r"(b1))

// ---- prepass: x -> tf32 bits; within-row order pos = (ci%4)*4 + ci/4 ----
__global__ __launch_bounds__(256)
void prep_x_kernel(const float* __restrict__ x) {
    const int d = blockIdx.x, l = blockIdx.y, n = blockIdx.z;
    const int tid = threadIdx.x;
    const size_t src0 = ((size_t)(n * 16) * 32 + l) * L_STRIDE + d * 576;
    uint32_t* dst0 = g_xp + (((size_t)(n * 32 + l) * 24 + d) * 576) * 16;
    for (int m = tid; m < 576; m += 256) {
        uint32_t v[16];
        #pragma unroll
        for (int ci = 0; ci < 16; ci++)
            v[(ci & 3) * 4 + (ci >> 2)] = tf32rn(x[src0 + (size_t)ci * (32 * L_STRIDE) + m]);
        uint32_t* dr = dst0 + m * 16;
        #pragma unroll
        for (int q = 0; q < 4; q++)
            *(uint4*)(dr + q * 4) = make_uint4(v[q*4], v[q*4+1], v[q*4+2], v[q*4+3]);
    }
}

// ---- prepass: W -> tf32 bits, [s][tap][co][pos=(ci%4)*4+ci/4] ----
__global__ __launch_bounds__(256)
void prep_w_kernel(const float* __restrict__ W) {
    int e = blockIdx.x * 256 + threadIdx.x;     // 0..41471
    int pos = e & 15;
    int co  = (e >> 4) & 31;
    int t9  = e >> 9;                            // s*9+tap
    int s   = t9 / 9, tap = t9 - 9 * s;
    int lk = s / 3,  dk = s - 3 * lk;
    int hk = tap / 3, wk = tap - 3 * hk;
    int ci = (pos & 3) + (pos >> 2) * 4;         // pos -> ci: quad c holds c,c+4,c+8,c+12
    ci = (pos >> 2) + (pos & 3) * 4;
    g_wp[e] = tf32rn(W[(size_t)(co * 16 + ci) * 81 + lk * 27 + dk * 9 + hk * 3 + wk]);
}

extern __shared__ char smem[];

__global__ __launch_bounds__(384)
void conv4d_mma_kernel(const float* __restrict__ b, float* __restrict__ out)
{
    const int d_out = blockIdx.x;   // 0..21
    const int l_out = blockIdx.y;   // 0..29
    const int n     = blockIdx.z;   // 0..7
    const int tid   = threadIdx.x;
    const int wid   = tid >> 5;     // 0..11
    const int lid   = tid & 31;
    const int c     = lid & 3;
    const int g     = lid >> 2;
    const uint32_t sb = s2u(smem);

    if (tid < 32) ((float*)(smem + OFF_BS))[tid] = 3.0f * b[tid];

    auto stage = [&](int s) {
        const int lk = s / 3, dk = s - 3 * lk;
        const uint32_t xo = sb + ((s & 1) ? OFF_X1 : OFF_X0);
        const uint32_t wo = sb + ((s & 1) ? OFF_W1 : OFF_W0);
        const uint32_t* xs = g_xp + (((size_t)(n * 32 + (l_out + lk)) * 24 + (d_out + dk)) * 576) * 16;
        #pragma unroll
        for (int j6 = 0; j6 < 6; j6++) {
            int j = tid + j6 * 384;              // 0..2303  (m 0..575, q 0..3)
            cp16(xo + (uint32_t)(j * 16), xs + (size_t)j * 4);
        }
        const uint32_t* wsrc = g_wp + s * 4608;
        #pragma unroll
        for (int j3 = 0; j3 < 3; j3++) {
            int j = tid + j3 * 384;              // 0..1151
            cp16(wo + (uint32_t)(j * 16), wsrc + j * 4);
        }
        asm volatile("cp.async.commit_group;" ::: "memory");
    };

    const int cnt = (wid < 9) ? 3 : 2;           // tiles: t = wid + 12*i, 33 tiles

    float acc[3][4][4];
    #pragma unroll
    for (int mt = 0; mt < 3; mt++)
        #pragma unroll
        for (int nt = 0; nt < 4; nt++)
            #pragma unroll
            for (int q = 0; q < 4; q++)
                acc[mt][nt][q] = 0.0f;

    stage(0);

    for (int s = 0; s < 9; s++) {
        if (s < 8) {
            stage(s + 1);
            asm volatile("cp.async.wait_group 1;" ::: "memory");
        } else {
            asm volatile("cp.async.wait_group 0;" ::: "memory");
        }
        __syncthreads();

        const uint32_t xb = sb + ((s & 1) ? OFF_X1 : OFF_X0);
        const uint32_t wb = sb + ((s & 1) ? OFF_W1 : OFF_W0);

        #pragma unroll
        for (int tap = 0; tap < 9; tap++) {
            const int hk = tap / 3;
            const int tapoff = hk * 24 + (tap - 3 * hk);
            // B: row co = nt*8+g, 64B rows; quad c -> k = c, c+4 (kc0) / c+8, c+12 (kc1)
            uint32_t w0[4], w1[4], w2[4], w3[4];
            {
                const uint32_t wrow = wb + (uint32_t)(((tap * 32 + g) * 16 + c * 4) * 4);
                lds4(w0[0], w1[0], w2[0], w3[0], wrow);
                lds4(w0[1], w1[1], w2[1], w3[1], wrow + 8 * 64);
                lds4(w0[2], w1[2], w2[2], w3[2], wrow + 16 * 64);
                lds4(w0[3], w1[3], w2[3], w3[3], wrow + 24 * 64);
            }
            const uint32_t xrow = xb + (uint32_t)(((g + tapoff) * 16 + c * 4) * 4);
            #pragma unroll
            for (int mt = 0; mt < 3; mt++) {
                if (mt >= cnt) break;
                const int m0 = (wid + 12 * mt) * 16;
                uint32_t l0, l1, l2, l3, h0, h1, h2, h3;
                lds4(l0, l1, l2, l3, xrow + m0 * 64);
                lds4(h0, h1, h2, h3, xrow + (m0 + 8) * 64);
                #pragma unroll
                for (int nt = 0; nt < 4; nt++)
                    MMA_TF32(acc[mt][nt], l0, h0, l1, h1, w0[nt], w1[nt]);
                #pragma unroll
                for (int nt = 0; nt < 4; nt++)
                    MMA_TF32(acc[mt][nt], l2, h2, l3, h3, w2[nt], w3[nt]);
            }
        }
        __syncthreads();
    }

    // ---- epilogue ----
    const float* bs = (const float*)(smem + OFF_BS);
    const int spat = l_out * 10648 + d_out * 484;
    for (int mt = 0; mt < cnt; mt++) {
        const int mb = (wid + 12 * mt) * 16 + g;
        #pragma unroll
        for (int hm = 0; hm < 2; hm++) {
            int m = mb + 8 * hm;
            int h = m / 24;
            int w = m - 24 * h;
            if (h < 22 && w < 22) {
                size_t pos = (size_t)spat + h * 22 + w;
                #pragma unroll
                for (int nt = 0; nt < 4; nt++) {
                    #pragma unroll
                    for (int hc = 0; hc < 2; hc++) {
                        int co = nt * 8 + 2 * c + hc;
                        out[(size_t)(n * 32 + co) * OUT_CO_STRIDE + pos] =
                            acc[mt][nt][hm * 2 + hc] + bs[co];
                    }
                }
            }
        }
    }
}

extern "C" void kernel_launch(void* const* d_in, const int* in_sizes, int n_in,
                              void* d_out, int out_size)
{
    const float* x = (const float*)d_in[0];
    const float* W = (const float*)d_in[1];
    const float* b = (const float*)d_in[2];
    float* out = (float*)d_out;

    dim3 pgrid(24, 32, 8);
    prep_x_kernel<<<pgrid, 256>>>(x);
    prep_w_kernel<<<162, 256>>>(W);

    cudaFuncSetAttribute(conv4d_mma_kernel,
                         cudaFuncAttributeMaxDynamicSharedMemorySize, SMEM_TOTAL);
    dim3 grid(22, 30, 8);   // (d_out, l_out, n)
    conv4d_mma_kernel<<<grid, 384, SMEM_TOTAL>>>(b, out);
}